// round 1
// baseline (speedup 1.0000x reference)
#include <cuda_runtime.h>
#include <math.h>

#define HW    4096
#define CDIM  684
#define NP    512
#define BS    16
#define KREAL 805      // 684 channels + 121 conv taps
#define KPAD  816      // padded to multiple of 16

// -------- device scratch (no allocations allowed) --------
__device__ float g_beta [BS * HW];        // 256 KB
__device__ float g_Afull[KPAD * NP];      // 1.63 MB  [k][p]: rows 0..683 = Ua^T, 684..804 = Weff^T, rest 0
__device__ float g_qe   [BS * NP];        // per-(b,p) constant: query + all biases folded
__device__ float g_e    [BS * HW];        // e_t, then exp(e_t) in-place
__device__ float g_S    [BS];             // softmax denominator (+1e-8)

// ---------------- prep kernels ----------------

__global__ void beta_kernel(const float* __restrict__ alpha) {
    int idx = blockIdx.x * blockDim.x + threadIdx.x;
    if (idx < BS * HW) {
        int b = idx >> 12, n = idx & (HW - 1);
        const float* a = alpha + (size_t)b * 4 * HW + n;
        g_beta[idx] = a[0] + a[HW] + a[2 * HW] + a[3 * HW];
    }
}

// rows 0..683 of Afull: transpose of convUa_w [512,684] -> [684,512]
__global__ void uat_kernel(const float* __restrict__ ua) {
    int idx = blockIdx.x * blockDim.x + threadIdx.x;
    if (idx < CDIM * NP) {
        int c = idx >> 9, p = idx & (NP - 1);
        g_Afull[idx] = ua[p * CDIM + c];
    }
}

// rows 684..815: Weff^T[tap][p] = sum_q Uf_w[p,q]*convQ_w[q,tap]; pad rows (tap>=121) = 0
__global__ void weff_kernel(const float* __restrict__ ufw, const float* __restrict__ cqw) {
    int idx = blockIdx.x * blockDim.x + threadIdx.x;
    if (idx < (KPAD - CDIM) * NP) {
        int tap = idx >> 9, p = idx & (NP - 1);
        float s = 0.f;
        if (tap < 121) {
            for (int q = 0; q < 256; q++)
                s = fmaf(ufw[p * 256 + q], cqw[q * 121 + tap], s);
        }
        g_Afull[(CDIM + tap) * NP + p] = s;
    }
}

// qe[b,p] = st_hat[b]·Wa_w[p] + Wa_b[p] + convUa_b[p] + Uf_b[p] + sum_q Uf_w[p,q]*convQ_b[q]
__global__ void qe_kernel(const float* __restrict__ st_hat, const float* __restrict__ waw,
                          const float* __restrict__ wab, const float* __restrict__ uab,
                          const float* __restrict__ ufw, const float* __restrict__ ufb,
                          const float* __restrict__ cqb) {
    int idx = blockIdx.x * blockDim.x + threadIdx.x;
    if (idx < BS * NP) {
        int b = idx >> 9, p = idx & (NP - 1);
        float s = wab[p] + uab[p] + ufb[p];
        for (int n = 0; n < 256; n++)
            s = fmaf(st_hat[b * 256 + n], waw[p * 256 + n], s);
        for (int q = 0; q < 256; q++)
            s = fmaf(ufw[p * 256 + q], cqb[q], s);
        g_qe[idx] = s;
    }
}

// ---------------- main fused score kernel ----------------
// One block = (batch b, 64-pixel tile). GEMM 512p x 64pix over K=816,
// where K rows 0..683 = x channels, 684..804 = beta conv taps.
// Epilogue: tanh(acc + qe[p]) * Va[p], fixed-order tree reduce over p -> e.
__global__ __launch_bounds__(512, 1)
void score_kernel(const float* __restrict__ x, const float* __restrict__ vaw,
                  const float* __restrict__ vab) {
    __shared__ float As[16][NP];      // 32 KB (reused as 64x65 reduction buf)
    __shared__ float Bs[16][64];      // 4 KB
    __shared__ float betaT[11][80];   // 3.5 KB
    __shared__ float qe_s[NP];
    __shared__ float va_s[NP];

    const int b    = blockIdx.y;
    const int tile = blockIdx.x;          // 0..63
    const int y    = tile >> 1;           // row 0..31
    const int xb0  = (tile & 1) << 6;     // 0 or 64
    const int pixbase = y * 128 + xb0;
    const int tid  = threadIdx.x;

    qe_s[tid] = g_qe[b * NP + tid];
    va_s[tid] = vaw[tid];

    // beta neighborhood tile: rows y-5..y+5, cols xb0-5..xb0+68 (74 wide, zero-padded)
    for (int i = tid; i < 11 * 80; i += 512) {
        int ry = i / 80, cx = i - ry * 80;
        int yy = y + ry - 5, xx = xb0 + cx - 5;
        float v = 0.f;
        if (yy >= 0 && yy < 32 && xx >= 0 && xx < 128 && cx < 74)
            v = g_beta[b * HW + yy * 128 + xx];
        betaT[ry][cx] = v;
    }

    const int tp = tid >> 3;   // 0..63: p-block (8 p's)
    const int tx = tid & 7;    // 0..7 : pixel-block (8 pixels)

    float acc[8][8];
#pragma unroll
    for (int r = 0; r < 8; r++)
#pragma unroll
        for (int c = 0; c < 8; c++) acc[r][c] = 0.f;

    const float* xb = x + (size_t)b * CDIM * HW + pixbase;
    __syncthreads();

    for (int kc = 0; kc < KPAD / 16; kc++) {
        const int k0 = kc * 16;
#pragma unroll
        for (int l = 0; l < 16; l++)
            As[l][tid] = g_Afull[(k0 + l) * NP + tid];
#pragma unroll
        for (int l = 0; l < 2; l++) {
            int lin = tid + l * 512;
            int i = lin >> 6, j = lin & 63;
            int k = k0 + i;
            float v = 0.f;
            if (k < CDIM) {
                v = xb[(size_t)k * HW + j];
            } else if (k < KREAL) {
                int tap = k - CDIM;
                int dy = tap / 11, dx = tap - dy * 11;
                v = betaT[dy][j + dx];
            }
            Bs[i][j] = v;
        }
        __syncthreads();
#pragma unroll
        for (int i = 0; i < 16; i++) {
            float4 a0 = *(const float4*)&As[i][tp * 8];
            float4 a1 = *(const float4*)&As[i][tp * 8 + 4];
            float4 b0 = *(const float4*)&Bs[i][tx * 8];
            float4 b1 = *(const float4*)&Bs[i][tx * 8 + 4];
            float av[8] = {a0.x, a0.y, a0.z, a0.w, a1.x, a1.y, a1.z, a1.w};
            float bv[8] = {b0.x, b0.y, b0.z, b0.w, b1.x, b1.y, b1.z, b1.w};
#pragma unroll
            for (int r = 0; r < 8; r++)
#pragma unroll
                for (int c = 0; c < 8; c++)
                    acc[r][c] = fmaf(av[r], bv[c], acc[r][c]);
        }
        __syncthreads();
    }

    // epilogue: partial e over this thread's 8 p's for its 8 pixels
    float part[8];
#pragma unroll
    for (int c = 0; c < 8; c++) part[c] = 0.f;
#pragma unroll
    for (int r = 0; r < 8; r++) {
        int p = tp * 8 + r;
        float q  = qe_s[p];
        float va = va_s[p];
#pragma unroll
        for (int c = 0; c < 8; c++)
            part[c] = fmaf(va, tanhf(acc[r][c] + q), part[c]);
    }

    // fixed-order reduction over 64 p-blocks (alias As as 64x65)
    float* red = &As[0][0];
#pragma unroll
    for (int c = 0; c < 8; c++)
        red[tp * 65 + tx * 8 + c] = part[c];
    __syncthreads();
    if (tid < 64) {
        float s = 0.f;
        for (int r = 0; r < 64; r++) s += red[r * 65 + tid];
        g_e[b * HW + pixbase + tid] = s + vab[0];
    }
}

// ---------------- softmax (exp + sum), per batch ----------------
__global__ void softmax_kernel() {
    int b = blockIdx.x;
    int tid = threadIdx.x;
    __shared__ float red[256];
    float* eb = g_e + b * HW;
    float local = 0.f;
    for (int i = tid; i < HW; i += 256) {
        float v = expf(eb[i]);
        eb[i] = v;
        local += v;
    }
    red[tid] = local;
    __syncthreads();
    for (int s = 128; s > 0; s >>= 1) {
        if (tid < s) red[tid] += red[tid + s];
        __syncthreads();
    }
    if (tid == 0) g_S[b] = red[0] + 1e-8f;
}

// alpha_t = exp(e)/S  -> output region 2
__global__ void alpha_kernel(float* __restrict__ out_alpha) {
    int idx = blockIdx.x * blockDim.x + threadIdx.x;
    if (idx < BS * HW) out_alpha[idx] = g_e[idx] / g_S[idx >> 12];
}

// context[b,c] = (sum_hw exp(e)*x) / S  -> output region 1
__global__ void context_kernel(const float* __restrict__ x, float* __restrict__ out) {
    int c = blockIdx.x, b = blockIdx.y;
    const float* xr = x + ((size_t)b * CDIM + c) * HW;
    const float* er = g_e + b * HW;
    float s = 0.f;
    for (int i = threadIdx.x; i < HW; i += 128) s = fmaf(xr[i], er[i], s);
    __shared__ float red[128];
    red[threadIdx.x] = s;
    __syncthreads();
    for (int st = 64; st > 0; st >>= 1) {
        if (threadIdx.x < st) red[threadIdx.x] += red[threadIdx.x + st];
        __syncthreads();
    }
    if (threadIdx.x == 0) out[b * CDIM + c] = red[0] / g_S[b];
}

// ---------------- launch ----------------
extern "C" void kernel_launch(void* const* d_in, const int* in_sizes, int n_in,
                              void* d_out, int out_size) {
    const float* x        = (const float*)d_in[0];
    const float* st_hat   = (const float*)d_in[1];
    const float* alpha    = (const float*)d_in[2];
    const float* convQ_w  = (const float*)d_in[3];
    const float* convQ_b  = (const float*)d_in[4];
    const float* Wa_w     = (const float*)d_in[5];
    const float* Wa_b     = (const float*)d_in[6];
    const float* convUa_w = (const float*)d_in[7];
    const float* convUa_b = (const float*)d_in[8];
    const float* Uf_w     = (const float*)d_in[9];
    const float* Uf_b     = (const float*)d_in[10];
    const float* Va_w     = (const float*)d_in[11];
    const float* Va_b     = (const float*)d_in[12];

    float* out_ctx   = (float*)d_out;            // [16,684]
    float* out_alpha = (float*)d_out + BS * CDIM; // [16,1,32,128]

    beta_kernel<<<(BS * HW + 1023) / 1024, 1024>>>(alpha);
    uat_kernel<<<(CDIM * NP + 255) / 256, 256>>>(convUa_w);
    weff_kernel<<<((KPAD - CDIM) * NP + 255) / 256, 256>>>(Uf_w, convQ_w);
    qe_kernel<<<(BS * NP + 255) / 256, 256>>>(st_hat, Wa_w, Wa_b, convUa_b,
                                              Uf_w, Uf_b, convQ_b);
    dim3 gs(64, BS);
    score_kernel<<<gs, 512>>>(x, Va_w, Va_b);
    softmax_kernel<<<BS, 256>>>();
    alpha_kernel<<<(BS * HW + 255) / 256, 256>>>(out_alpha);
    dim3 gc(CDIM, BS);
    context_kernel<<<gc, 128>>>(x, out_ctx);
}

// round 4
// speedup vs baseline: 2.8279x; 2.8279x over previous
#include <cuda_runtime.h>
#include <cstdint>
#include <math.h>

#define HW    4096
#define CDIM  684
#define NP    512
#define BS    16
#define KPAD  832            // 684 channels + 121 taps + 27 zero pad
#define NCHUNK 52            // K chunks of 16
#define TAPPAD 148
#define AS_STRIDE 20         // floats per A row in smem (16 data + pad)
#define BS_STRIDE 136        // floats per B row in smem (128 data + pad)
#define STAGEF (256 * AS_STRIDE + 16 * BS_STRIDE)   // 7296 floats per stage

// -------- device scratch --------
__device__ float g_beta [BS * HW];
__device__ float g_A    [NP * KPAD];      // [p][k] row-major
__device__ float g_qe   [BS * NP];
__device__ float g_epart[2][BS * HW];     // per-p-half partial e
__device__ float g_e    [BS * HW];        // exp(e)
__device__ float g_S    [BS];

// ================= prep kernels =================

__global__ void beta_kernel(const float* __restrict__ alpha) {
    int idx = blockIdx.x * blockDim.x + threadIdx.x;
    if (idx < BS * HW) {
        int b = idx >> 12, n = idx & (HW - 1);
        const float* a = alpha + (size_t)b * 4 * HW + n;
        g_beta[idx] = a[0] + a[HW] + a[2 * HW] + a[3 * HW];
    }
}

__global__ void copyUa_kernel(const float* __restrict__ ua) {
    int idx = blockIdx.x * blockDim.x + threadIdx.x;
    if (idx < NP * CDIM) {
        int p = idx / CDIM, c = idx - p * CDIM;
        g_A[p * KPAD + c] = ua[idx];
    }
}

// g_A[p][684+tap] = sum_q Uf[p,q]*convQ[q,tap]; tap>=121 -> 0. Warp per output.
__global__ void weff_kernel(const float* __restrict__ ufw, const float* __restrict__ cqw) {
    int w = (blockIdx.x * blockDim.x + threadIdx.x) >> 5;
    int lane = threadIdx.x & 31;
    if (w >= NP * TAPPAD) return;
    int p = w / TAPPAD, t = w - p * TAPPAD;
    float s = 0.f;
    if (t < 121) {
        for (int q = lane; q < 256; q += 32)
            s = fmaf(ufw[p * 256 + q], cqw[q * 121 + t], s);
    }
#pragma unroll
    for (int o = 16; o > 0; o >>= 1) s += __shfl_down_sync(0xFFFFFFFFu, s, o);
    if (lane == 0) g_A[p * KPAD + CDIM + t] = s;
}

__global__ void qe_kernel(const float* __restrict__ st_hat, const float* __restrict__ waw,
                          const float* __restrict__ wab, const float* __restrict__ uab,
                          const float* __restrict__ ufw, const float* __restrict__ ufb,
                          const float* __restrict__ cqb) {
    int w = (blockIdx.x * blockDim.x + threadIdx.x) >> 5;
    int lane = threadIdx.x & 31;
    if (w >= BS * NP) return;
    int b = w >> 9, p = w & (NP - 1);
    float s = 0.f;
    for (int i = lane; i < 256; i += 32) {
        s = fmaf(st_hat[b * 256 + i], waw[p * 256 + i], s);
        s = fmaf(ufw[p * 256 + i], cqb[i], s);
    }
#pragma unroll
    for (int o = 16; o > 0; o >>= 1) s += __shfl_down_sync(0xFFFFFFFFu, s, o);
    if (lane == 0) g_qe[w] = s + wab[p] + uab[p] + ufb[p];
}

// ================= mma.sync TF32 score kernel =================
// CTA = (b, y-row tile of 128 pix, p-half). D[256p x 128pix] via m16n8k8 tf32.
// 16 warps: warp_m = wid&3 (64 p), warp_n = wid>>2 (32 pix).
__global__ __launch_bounds__(512, 1)
void score_kernel(const float* __restrict__ x, const float* __restrict__ vaw) {
    extern __shared__ float sm[];
    __shared__ float betaT[11][144];
    __shared__ float qe_s[256], va_s[256];
    __shared__ float red[4][128];

    const int tid = threadIdx.x;
    const int wid = tid >> 5, lane = tid & 31;
    const int warp_m = wid & 3, warp_n = wid >> 2;
    const int g = lane >> 2, ti = lane & 3;
    const int b = blockIdx.y, tileY = blockIdx.x, pz = blockIdx.z;
    const int pixbase = tileY * 128;

    if (tid < 256) {
        qe_s[tid] = g_qe[b * NP + pz * 256 + tid];
        va_s[tid] = vaw[pz * 256 + tid];
    }
    // beta row neighborhood: rows tileY-5..tileY+5, cols -5..138
    for (int i = tid; i < 11 * 144; i += 512) {
        int ry = i / 144, cx = i - ry * 144;
        int yy = tileY + ry - 5, xx = cx - 5;
        float v = 0.f;
        if (yy >= 0 && yy < 32 && xx >= 0 && xx < 128)
            v = g_beta[b * HW + yy * 128 + xx];
        betaT[ry][cx] = v;
    }
    __syncthreads();

    const float* xb = x + (size_t)b * CDIM * HW + pixbase;
    const float* Ab = g_A + (size_t)(pz * 256) * KPAD;

    // prefetch registers
    float4 pa0, pa1, pb;
    const int ar0 = tid >> 2, aq0 = (tid & 3) * 4;
    const int ar1 = (tid + 512) >> 2, aq1 = ((tid + 512) & 3) * 4;
    const int brow = tid >> 5, bc4 = (tid & 31) * 4;

    auto loadAB = [&](int ch) {
        const int k0 = ch * 16;
        pa0 = *(const float4*)(Ab + (size_t)ar0 * KPAD + k0 + aq0);
        pa1 = *(const float4*)(Ab + (size_t)ar1 * KPAD + k0 + aq1);
        int k = k0 + brow;
        if (k < CDIM) {
            pb = *(const float4*)(xb + (size_t)k * HW + bc4);
        } else {
            int tap = k - CDIM;
            if (tap < 121) {
                int dy = tap / 11, dx = tap - dy * 11;
                pb.x = betaT[dy][bc4 + 0 + dx];
                pb.y = betaT[dy][bc4 + 1 + dx];
                pb.z = betaT[dy][bc4 + 2 + dx];
                pb.w = betaT[dy][bc4 + 3 + dx];
            } else {
                pb = make_float4(0.f, 0.f, 0.f, 0.f);
            }
        }
    };

    float acc[4][4][4];
#pragma unroll
    for (int t = 0; t < 4; t++)
#pragma unroll
        for (int u = 0; u < 4; u++)
#pragma unroll
            for (int c = 0; c < 4; c++) acc[t][u][c] = 0.f;

    loadAB(0);

    for (int ch = 0; ch < NCHUNK; ch++) {
        float* Asb = sm + (ch & 1) * STAGEF;
        float* Bsb = Asb + 256 * AS_STRIDE;
        // store prefetched chunk
        {
            float* a = Asb + ar0 * AS_STRIDE + aq0;
            a[0] = pa0.x; a[1] = pa0.y; a[2] = pa0.z; a[3] = pa0.w;
            float* a2 = Asb + ar1 * AS_STRIDE + aq1;
            a2[0] = pa1.x; a2[1] = pa1.y; a2[2] = pa1.z; a2[3] = pa1.w;
            *(float4*)(Bsb + brow * BS_STRIDE + bc4) = pb;
        }
        __syncthreads();
        if (ch < NCHUNK - 1) loadAB(ch + 1);

        const float* Aw = Asb + warp_m * 64 * AS_STRIDE;
        const float* Bw = Bsb + warp_n * 32;
#pragma unroll
        for (int ks = 0; ks < 2; ks++) {
            const int kb = ks * 8;
            uint32_t a[4][4], bb[4][2];
#pragma unroll
            for (int t = 0; t < 4; t++) {
                const float* ap = Aw + (t * 16 + g) * AS_STRIDE + kb + ti;
                a[t][0] = __float_as_uint(ap[0]);
                a[t][1] = __float_as_uint(ap[8 * AS_STRIDE]);
                a[t][2] = __float_as_uint(ap[4]);
                a[t][3] = __float_as_uint(ap[8 * AS_STRIDE + 4]);
            }
#pragma unroll
            for (int u = 0; u < 4; u++) {
                const float* bp = Bw + (kb + ti) * BS_STRIDE + u * 8 + g;
                bb[u][0] = __float_as_uint(bp[0]);
                bb[u][1] = __float_as_uint(bp[4 * BS_STRIDE]);
            }
#pragma unroll
            for (int t = 0; t < 4; t++)
#pragma unroll
                for (int u = 0; u < 4; u++)
                    asm volatile(
                        "mma.sync.aligned.m16n8k8.row.col.f32.tf32.tf32.f32 "
                        "{%0,%1,%2,%3}, {%4,%5,%6,%7}, {%8,%9}, {%0,%1,%2,%3};"
                        : "+f"(acc[t][u][0]), "+f"(acc[t][u][1]),
                          "+f"(acc[t][u][2]), "+f"(acc[t][u][3])
                        : "r"(a[t][0]), "r"(a[t][1]), "r"(a[t][2]), "r"(a[t][3]),
                          "r"(bb[u][0]), "r"(bb[u][1]));
        }
        __syncthreads();
    }

    // epilogue: va*tanh(acc+qe), reduce over p
    float part[4][2];
#pragma unroll
    for (int u = 0; u < 4; u++) { part[u][0] = 0.f; part[u][1] = 0.f; }
#pragma unroll
    for (int t = 0; t < 4; t++) {
        const int p0 = warp_m * 64 + t * 16 + g;
        const float q0 = qe_s[p0],     v0 = va_s[p0];
        const float q1 = qe_s[p0 + 8], v1 = va_s[p0 + 8];
#pragma unroll
        for (int u = 0; u < 4; u++) {
            part[u][0] = fmaf(v0, tanhf(acc[t][u][0] + q0), part[u][0]);
            part[u][1] = fmaf(v0, tanhf(acc[t][u][1] + q0), part[u][1]);
            part[u][0] = fmaf(v1, tanhf(acc[t][u][2] + q1), part[u][0]);
            part[u][1] = fmaf(v1, tanhf(acc[t][u][3] + q1), part[u][1]);
        }
    }
#pragma unroll
    for (int u = 0; u < 4; u++)
#pragma unroll
        for (int j = 0; j < 2; j++) {
            part[u][j] += __shfl_down_sync(0xFFFFFFFFu, part[u][j], 16);
            part[u][j] += __shfl_down_sync(0xFFFFFFFFu, part[u][j], 8);
            part[u][j] += __shfl_down_sync(0xFFFFFFFFu, part[u][j], 4);
        }
    if (lane < 4) {
#pragma unroll
        for (int u = 0; u < 4; u++)
#pragma unroll
            for (int j = 0; j < 2; j++)
                red[warp_m][warp_n * 32 + u * 8 + ti * 2 + j] = part[u][j];
    }
    __syncthreads();
    if (tid < 128) {
        float s = red[0][tid] + red[1][tid] + red[2][tid] + red[3][tid];
        g_epart[pz][b * HW + pixbase + tid] = s;
    }
}

// ================= softmax / outputs =================
__global__ void softmax_kernel(const float* __restrict__ vab) {
    int b = blockIdx.x, tid = threadIdx.x;
    __shared__ float red[256];
    const float vb = vab[0];
    float local = 0.f;
    for (int i = tid; i < HW; i += 256) {
        int idx = b * HW + i;
        float v = expf(g_epart[0][idx] + g_epart[1][idx] + vb);
        g_e[idx] = v;
        local += v;
    }
    red[tid] = local;
    __syncthreads();
    for (int s = 128; s > 0; s >>= 1) {
        if (tid < s) red[tid] += red[tid + s];
        __syncthreads();
    }
    if (tid == 0) g_S[b] = red[0] + 1e-8f;
}

__global__ void alpha_kernel(float* __restrict__ out_alpha) {
    int idx = blockIdx.x * blockDim.x + threadIdx.x;
    if (idx < BS * HW) out_alpha[idx] = g_e[idx] / g_S[idx >> 12];
}

__global__ void context_kernel(const float* __restrict__ x, float* __restrict__ out) {
    int c = blockIdx.x, b = blockIdx.y;
    const float* xr = x + ((size_t)b * CDIM + c) * HW;
    const float* er = g_e + b * HW;
    float s = 0.f;
    for (int i = threadIdx.x; i < HW; i += 128) s = fmaf(xr[i], er[i], s);
    __shared__ float red[128];
    red[threadIdx.x] = s;
    __syncthreads();
    for (int st = 64; st > 0; st >>= 1) {
        if (threadIdx.x < st) red[threadIdx.x] += red[threadIdx.x + st];
        __syncthreads();
    }
    if (threadIdx.x == 0) out[b * CDIM + c] = red[0] / g_S[b];
}

// ================= launch =================
extern "C" void kernel_launch(void* const* d_in, const int* in_sizes, int n_in,
                              void* d_out, int out_size) {
    const float* x        = (const float*)d_in[0];
    const float* st_hat   = (const float*)d_in[1];
    const float* alpha    = (const float*)d_in[2];
    const float* convQ_w  = (const float*)d_in[3];
    const float* convQ_b  = (const float*)d_in[4];
    const float* Wa_w     = (const float*)d_in[5];
    const float* Wa_b     = (const float*)d_in[6];
    const float* convUa_w = (const float*)d_in[7];
    const float* convUa_b = (const float*)d_in[8];
    const float* Uf_w     = (const float*)d_in[9];
    const float* Uf_b     = (const float*)d_in[10];
    const float* Va_w     = (const float*)d_in[11];
    const float* Va_b     = (const float*)d_in[12];

    float* out_ctx   = (float*)d_out;
    float* out_alpha = (float*)d_out + BS * CDIM;

    const int dyn_bytes = 2 * STAGEF * sizeof(float);   // ~58.4 KB
    cudaFuncSetAttribute(score_kernel, cudaFuncAttributeMaxDynamicSharedMemorySize,
                         dyn_bytes);

    beta_kernel<<<(BS * HW + 1023) / 1024, 1024>>>(alpha);
    copyUa_kernel<<<(NP * CDIM + 255) / 256, 256>>>(convUa_w);
    weff_kernel<<<(NP * TAPPAD * 32 + 255) / 256, 256>>>(Uf_w, convQ_w);
    qe_kernel<<<(BS * NP * 32 + 255) / 256, 256>>>(st_hat, Wa_w, Wa_b, convUa_b,
                                                   Uf_w, Uf_b, convQ_b);
    {
        dim3 gs(HW / 128, BS, 2);
        score_kernel<<<gs, 512, dyn_bytes>>>(x, Va_w);
    }
    softmax_kernel<<<BS, 256>>>(Va_b);
    alpha_kernel<<<(BS * HW + 255) / 256, 256>>>(out_alpha);
    {
        dim3 gc(CDIM, BS);
        context_kernel<<<gc, 128>>>(x, out_ctx);
    }
}

// round 7
// speedup vs baseline: 2.8546x; 1.0095x over previous
#include <cuda_runtime.h>
#include <cuda_fp16.h>
#include <cstdint>
#include <math.h>

#define HW    4096
#define CDIM  684
#define NP    512
#define BS    16
#define KPAD  832            // 684 channels + 121 taps + 27 zero pad
#define NCHUNK 52            // K chunks of 16
#define TAPPAD 148

// smem stage layout (bytes)
#define A_ROW_B   48         // 16 halves (32B) + 16B pad  -> conflict-free ldmatrix
#define B_ROW_B   272        // 128 halves (256B) + 16B pad
#define A_STAGE_B (256 * A_ROW_B)            // 12288
#define B_STAGE_B (16 * B_ROW_B)             // 4352
#define STAGE_B   (A_STAGE_B + B_STAGE_B)    // 16640
#define NSTAGES   4

// -------- device scratch --------
__device__ __half g_Ah  [NP * KPAD];                 // weights fp16 [p][k]
__device__ __half g_Bh  [(size_t)BS * KPAD * HW];    // 109 MB: rows 0..683 fp16(x), 684..831 taps
__device__ float  g_qe  [BS * NP];
__device__ float  g_epart[2][BS * HW];
__device__ float  g_e   [BS * HW];
__device__ float  g_S   [BS];

__device__ __forceinline__ uint32_t smem_u32(const void* p) {
    uint32_t a;
    asm("{ .reg .u64 t; cvta.to.shared.u64 t, %1; cvt.u32.u64 %0, t; }" : "=r"(a) : "l"(p));
    return a;
}

// ================= prep kernels =================

// g_Bh x-part: fp16 convert, same [c][pix] ordering per batch
__global__ void convx_kernel(const float* __restrict__ x) {
    int b = blockIdx.y;
    int i4 = blockIdx.x * blockDim.x + threadIdx.x;          // over 684*1024 float4s
    if (i4 >= CDIM * (HW / 4)) return;
    int c = i4 >> 10, pixq = i4 & 1023;
    float4 v = *(const float4*)(x + ((size_t)b * CDIM + c) * HW + pixq * 4);
    __half2 h0 = __floats2half2_rn(v.x, v.y);
    __half2 h1 = __floats2half2_rn(v.z, v.w);
    __half2* dst = (__half2*)(g_Bh + ((size_t)b * KPAD + c) * HW + pixq * 4);
    dst[0] = h0; dst[1] = h1;
}

// g_Bh tap rows: tap t at k=684+t, value = beta[b][y+dy-5][x+dx-5] (sum of 4 alpha), 0 if OOB or t>=121
__global__ void taps_kernel(const float* __restrict__ alpha) {
    int b = blockIdx.y;
    int j = blockIdx.x * blockDim.x + threadIdx.x;           // over 148*4096
    if (j >= TAPPAD * HW) return;
    int t = j >> 12, pix = j & (HW - 1);
    float v = 0.f;
    if (t < 121) {
        int dy = t / 11, dx = t - dy * 11;
        int y = (pix >> 7) + dy - 5, xx = (pix & 127) + dx - 5;
        if (y >= 0 && y < 32 && xx >= 0 && xx < 128) {
            const float* a = alpha + (size_t)b * 4 * HW + y * 128 + xx;
            v = a[0] + a[HW] + a[2 * HW] + a[3 * HW];
        }
    }
    g_Bh[((size_t)b * KPAD + CDIM + t) * HW + pix] = __float2half_rn(v);
}

__global__ void copyUa_kernel(const float* __restrict__ ua) {
    int idx = blockIdx.x * blockDim.x + threadIdx.x;
    if (idx < NP * CDIM) {
        int p = idx / CDIM, c = idx - p * CDIM;
        g_Ah[p * KPAD + c] = __float2half_rn(ua[idx]);
    }
}

__global__ void weff_kernel(const float* __restrict__ ufw, const float* __restrict__ cqw) {
    int w = (blockIdx.x * blockDim.x + threadIdx.x) >> 5;
    int lane = threadIdx.x & 31;
    if (w >= NP * TAPPAD) return;
    int p = w / TAPPAD, t = w - p * TAPPAD;
    float s = 0.f;
    if (t < 121) {
        for (int q = lane; q < 256; q += 32)
            s = fmaf(ufw[p * 256 + q], cqw[q * 121 + t], s);
    }
#pragma unroll
    for (int o = 16; o > 0; o >>= 1) s += __shfl_down_sync(0xFFFFFFFFu, s, o);
    if (lane == 0) g_Ah[p * KPAD + CDIM + t] = __float2half_rn(s);
}

__global__ void qe_kernel(const float* __restrict__ st_hat, const float* __restrict__ waw,
                          const float* __restrict__ wab, const float* __restrict__ uab,
                          const float* __restrict__ ufw, const float* __restrict__ ufb,
                          const float* __restrict__ cqb) {
    int w = (blockIdx.x * blockDim.x + threadIdx.x) >> 5;
    int lane = threadIdx.x & 31;
    if (w >= BS * NP) return;
    int b = w >> 9, p = w & (NP - 1);
    float s = 0.f;
    for (int i = lane; i < 256; i += 32) {
        s = fmaf(st_hat[b * 256 + i], waw[p * 256 + i], s);
        s = fmaf(ufw[p * 256 + i], cqb[i], s);
    }
#pragma unroll
    for (int o = 16; o > 0; o >>= 1) s += __shfl_down_sync(0xFFFFFFFFu, s, o);
    if (lane == 0) g_qe[w] = s + wab[p] + uab[p] + ufb[p];
}

// ================= fp16 mma score kernel =================
// CTA = (b, 128-pix tile, p-half). D[256p x 128pix], m16n8k16 fp16->fp32.
// 16 warps: warp_m = wid&3 (64 p), warp_n = wid>>2 (32 pix).
__global__ __launch_bounds__(512, 1)
void score_kernel(const float* __restrict__ vaw) {
    extern __shared__ char smem[];
    __shared__ float qe_s[256], va_s[256];
    __shared__ float red[4][128];

    const int tid = threadIdx.x;
    const int wid = tid >> 5, lane = tid & 31;
    const int warp_m = wid & 3, warp_n = wid >> 2;
    const int g = lane >> 2, ti = lane & 3;
    const int b = blockIdx.y, tileY = blockIdx.x, pz = blockIdx.z;
    const int pixbase = tileY * 128;

    const uint32_t sbase = smem_u32(smem);

    if (tid < 256) {
        qe_s[tid] = g_qe[b * NP + pz * 256 + tid];
        va_s[tid] = vaw[pz * 256 + tid];
    }

    // cp.async source/dest indices
    const int arow = tid >> 1, agp = tid & 1;                  // A: 512 x 16B
    const __half* Asrc0 = g_Ah + (size_t)(pz * 256 + arow) * KPAD + agp * 8;
    const uint32_t Adst = arow * A_ROW_B + agp * 16;
    const int brow = tid >> 4, bgp = tid & 15;                 // B: 256 x 16B (tid<256)
    const __half* Bsrc0 = g_Bh + ((size_t)b * KPAD + brow) * HW + pixbase + bgp * 8;
    const uint32_t Bdst = A_STAGE_B + brow * B_ROW_B + bgp * 16;

    auto issue = [&](int ch) {
        const uint32_t st = sbase + (ch & 3) * STAGE_B;
        asm volatile("cp.async.cg.shared.global [%0], [%1], 16;"
                     :: "r"(st + Adst), "l"(Asrc0 + ch * 16) : "memory");
        if (tid < 256)
            asm volatile("cp.async.cg.shared.global [%0], [%1], 16;"
                         :: "r"(st + Bdst), "l"(Bsrc0 + (size_t)ch * 16 * HW) : "memory");
        asm volatile("cp.async.commit_group;" ::: "memory");
    };

    issue(0); issue(1); issue(2);

    // ldmatrix per-thread address components
    const int mat = lane >> 3, mrow = lane & 7;
    const uint32_t aoff = (uint32_t)(warp_m * 64 + mrow + (mat & 1) * 8) * A_ROW_B + (mat >> 1) * 16;
    const uint32_t boff = A_STAGE_B + (uint32_t)(mrow + (mat & 1) * 8) * B_ROW_B
                        + (uint32_t)(warp_n * 32 + (mat >> 1) * 8) * 2;

    float acc[4][4][4];
#pragma unroll
    for (int t = 0; t < 4; t++)
#pragma unroll
        for (int u = 0; u < 4; u++)
#pragma unroll
            for (int c = 0; c < 4; c++) acc[t][u][c] = 0.f;

    for (int ch = 0; ch < NCHUNK; ch++) {
        if (ch + 3 < NCHUNK) {
            asm volatile("cp.async.wait_group 2;" ::: "memory");
        } else {
            asm volatile("cp.async.wait_group 0;" ::: "memory");
        }
        __syncthreads();
        if (ch + 3 < NCHUNK) issue(ch + 3);

        const uint32_t st = sbase + (ch & 3) * STAGE_B;
        uint32_t afr[4][4], bfr[2][4];
#pragma unroll
        for (int t = 0; t < 4; t++)
            asm volatile("ldmatrix.sync.aligned.m8n8.x4.shared.b16 {%0,%1,%2,%3}, [%4];"
                         : "=r"(afr[t][0]), "=r"(afr[t][1]), "=r"(afr[t][2]), "=r"(afr[t][3])
                         : "r"(st + aoff + t * 16 * A_ROW_B));
#pragma unroll
        for (int h = 0; h < 2; h++)
            asm volatile("ldmatrix.sync.aligned.m8n8.x4.trans.shared.b16 {%0,%1,%2,%3}, [%4];"
                         : "=r"(bfr[h][0]), "=r"(bfr[h][1]), "=r"(bfr[h][2]), "=r"(bfr[h][3])
                         : "r"(st + boff + h * 32));
#pragma unroll
        for (int t = 0; t < 4; t++)
#pragma unroll
            for (int u = 0; u < 4; u++) {
                const uint32_t b0 = bfr[u >> 1][(u & 1) * 2];
                const uint32_t b1 = bfr[u >> 1][(u & 1) * 2 + 1];
                asm volatile(
                    "mma.sync.aligned.m16n8k16.row.col.f32.f16.f16.f32 "
                    "{%0,%1,%2,%3}, {%4,%5,%6,%7}, {%8,%9}, {%0,%1,%2,%3};"
                    : "+f"(acc[t][u][0]), "+f"(acc[t][u][1]),
                      "+f"(acc[t][u][2]), "+f"(acc[t][u][3])
                    : "r"(afr[t][0]), "r"(afr[t][1]), "r"(afr[t][2]), "r"(afr[t][3]),
                      "r"(b0), "r"(b1));
            }
        __syncthreads();
    }

    // epilogue: va*tanh(acc+qe), reduce over p
    float part[4][2];
#pragma unroll
    for (int u = 0; u < 4; u++) { part[u][0] = 0.f; part[u][1] = 0.f; }
#pragma unroll
    for (int t = 0; t < 4; t++) {
        const int p0 = warp_m * 64 + t * 16 + g;
        const float q0 = qe_s[p0],     v0 = va_s[p0];
        const float q1 = qe_s[p0 + 8], v1 = va_s[p0 + 8];
#pragma unroll
        for (int u = 0; u < 4; u++) {
            part[u][0] = fmaf(v0, tanhf(acc[t][u][0] + q0), part[u][0]);
            part[u][1] = fmaf(v0, tanhf(acc[t][u][1] + q0), part[u][1]);
            part[u][0] = fmaf(v1, tanhf(acc[t][u][2] + q1), part[u][0]);
            part[u][1] = fmaf(v1, tanhf(acc[t][u][3] + q1), part[u][1]);
        }
    }
#pragma unroll
    for (int u = 0; u < 4; u++)
#pragma unroll
        for (int j = 0; j < 2; j++) {
            part[u][j] += __shfl_down_sync(0xFFFFFFFFu, part[u][j], 16);
            part[u][j] += __shfl_down_sync(0xFFFFFFFFu, part[u][j], 8);
            part[u][j] += __shfl_down_sync(0xFFFFFFFFu, part[u][j], 4);
        }
    if (lane < 4) {
#pragma unroll
        for (int u = 0; u < 4; u++)
#pragma unroll
            for (int j = 0; j < 2; j++)
                red[warp_m][warp_n * 32 + u * 8 + ti * 2 + j] = part[u][j];
    }
    __syncthreads();
    if (tid < 128) {
        float s = red[0][tid] + red[1][tid] + red[2][tid] + red[3][tid];
        g_epart[pz][b * HW + pixbase + tid] = s;
    }
}

// ================= softmax / outputs =================
__global__ void softmax_kernel(const float* __restrict__ vab) {
    int b = blockIdx.x, tid = threadIdx.x;
    __shared__ float red[256];
    const float vb = vab[0];
    float local = 0.f;
    for (int i = tid; i < HW; i += 256) {
        int idx = b * HW + i;
        float v = expf(g_epart[0][idx] + g_epart[1][idx] + vb);
        g_e[idx] = v;
        local += v;
    }
    red[tid] = local;
    __syncthreads();
    for (int s = 128; s > 0; s >>= 1) {
        if (tid < s) red[tid] += red[tid + s];
        __syncthreads();
    }
    if (tid == 0) g_S[b] = red[0] + 1e-8f;
}

__global__ void alpha_kernel(float* __restrict__ out_alpha) {
    int idx = blockIdx.x * blockDim.x + threadIdx.x;
    if (idx < BS * HW) out_alpha[idx] = g_e[idx] / g_S[idx >> 12];
}

// context from fp16 x copy (halved traffic)
__global__ void context_kernel(float* __restrict__ out) {
    int c = blockIdx.x, b = blockIdx.y;
    const __half2* xr = (const __half2*)(g_Bh + ((size_t)b * KPAD + c) * HW);
    const float* er = g_e + b * HW;
    float s = 0.f;
    for (int i = threadIdx.x; i < HW / 2; i += 128) {
        float2 xv = __half22float2(xr[i]);
        s = fmaf(xv.x, er[2 * i], s);
        s = fmaf(xv.y, er[2 * i + 1], s);
    }
    __shared__ float red[128];
    red[threadIdx.x] = s;
    __syncthreads();
    for (int st = 64; st > 0; st >>= 1) {
        if (threadIdx.x < st) red[threadIdx.x] += red[threadIdx.x + st];
        __syncthreads();
    }
    if (threadIdx.x == 0) out[b * CDIM + c] = red[0] / g_S[b];
}

// ================= launch =================
extern "C" void kernel_launch(void* const* d_in, const int* in_sizes, int n_in,
                              void* d_out, int out_size) {
    const float* x        = (const float*)d_in[0];
    const float* st_hat   = (const float*)d_in[1];
    const float* alpha    = (const float*)d_in[2];
    const float* convQ_w  = (const float*)d_in[3];
    const float* convQ_b  = (const float*)d_in[4];
    const float* Wa_w     = (const float*)d_in[5];
    const float* Wa_b     = (const float*)d_in[6];
    const float* convUa_w = (const float*)d_in[7];
    const float* convUa_b = (const float*)d_in[8];
    const float* Uf_w     = (const float*)d_in[9];
    const float* Uf_b     = (const float*)d_in[10];
    const float* Va_w     = (const float*)d_in[11];
    const float* Va_b     = (const float*)d_in[12];

    float* out_ctx   = (float*)d_out;
    float* out_alpha = (float*)d_out + BS * CDIM;

    const int dyn_bytes = NSTAGES * STAGE_B;   // 66560
    cudaFuncSetAttribute(score_kernel, cudaFuncAttributeMaxDynamicSharedMemorySize,
                         dyn_bytes);

    {   // launch 0
        dim3 g((CDIM * (HW / 4) + 255) / 256, BS);
        convx_kernel<<<g, 256>>>(x);
    }
    {   // launch 1
        dim3 g((TAPPAD * HW + 255) / 256, BS);
        taps_kernel<<<g, 256>>>(alpha);
    }
    copyUa_kernel<<<(NP * CDIM + 255) / 256, 256>>>(convUa_w);                    // 2
    weff_kernel<<<(NP * TAPPAD * 32 + 255) / 256, 256>>>(Uf_w, convQ_w);          // 3
    qe_kernel<<<(BS * NP * 32 + 255) / 256, 256>>>(st_hat, Wa_w, Wa_b, convUa_b,
                                                   Uf_w, Uf_b, convQ_b);          // 4
    {   // launch 5  (profiled by ncu -s 5 -c 1)
        dim3 gs(HW / 128, BS, 2);
        score_kernel<<<gs, 512, dyn_bytes>>>(Va_w);
    }
    softmax_kernel<<<BS, 256>>>(Va_b);                                            // 6
    alpha_kernel<<<(BS * HW + 255) / 256, 256>>>(out_alpha);                      // 7
    {   // launch 8
        dim3 gc(CDIM, BS);
        context_kernel<<<gc, 128>>>(out_ctx);
    }
}

// round 8
// speedup vs baseline: 4.7087x; 1.6495x over previous
#include <cuda_runtime.h>
#include <cuda_fp16.h>
#include <cstdint>
#include <math.h>

#define HW    4096
#define CDIM  684
#define NP    512
#define BS    16
#define KPAD  832            // 684 channels + 121 taps + 27 zero pad
#define NCHUNK 52            // K chunks of 16
#define TAPPAD 148

// smem stage layout (bytes)
#define A_ROW_B   48         // 16 halves (32B) + 16B pad
#define B_ROW_B   272        // 128 halves (256B) + 16B pad
#define A_STAGE_B (128 * A_ROW_B)            // 6144
#define B_STAGE_B (16 * B_ROW_B)             // 4352
#define STAGE_B   (A_STAGE_B + B_STAGE_B)    // 10496
#define NSTAGES   4

// -------- device scratch --------
__device__ __half g_Ah  [NP * KPAD];                 // weights fp16 [p][k]
__device__ __half g_Bh  [(size_t)BS * KPAD * HW];    // 109 MB
__device__ float  g_qe  [BS * NP];
__device__ float  g_epart[4][BS * HW];
__device__ float  g_e   [BS * HW];
__device__ float  g_S   [BS];

__device__ __forceinline__ uint32_t smem_u32(const void* p) {
    uint32_t a;
    asm("{ .reg .u64 t; cvta.to.shared.u64 t, %1; cvt.u32.u64 %0, t; }" : "=r"(a) : "l"(p));
    return a;
}

// ================= prep kernels =================

// launch 0: g_Bh x-part (fp16 convert)
__global__ void convx_kernel(const float* __restrict__ x) {
    int b = blockIdx.y;
    int i4 = blockIdx.x * blockDim.x + threadIdx.x;
    if (i4 >= CDIM * (HW / 4)) return;
    int c = i4 >> 10, pixq = i4 & 1023;
    float4 v = *(const float4*)(x + ((size_t)b * CDIM + c) * HW + pixq * 4);
    __half2* dst = (__half2*)(g_Bh + ((size_t)b * KPAD + c) * HW + pixq * 4);
    dst[0] = __floats2half2_rn(v.x, v.y);
    dst[1] = __floats2half2_rn(v.z, v.w);
}

// launch 1: g_Bh tap rows
__global__ void taps_kernel(const float* __restrict__ alpha) {
    int b = blockIdx.y;
    int j = blockIdx.x * blockDim.x + threadIdx.x;
    if (j >= TAPPAD * HW) return;
    int t = j >> 12, pix = j & (HW - 1);
    float v = 0.f;
    if (t < 121) {
        int dy = t / 11, dx = t - dy * 11;
        int y = (pix >> 7) + dy - 5, xx = (pix & 127) + dx - 5;
        if (y >= 0 && y < 32 && xx >= 0 && xx < 128) {
            const float* a = alpha + (size_t)b * 4 * HW + y * 128 + xx;
            v = a[0] + a[HW] + a[2 * HW] + a[3 * HW];
        }
    }
    g_Bh[((size_t)b * KPAD + CDIM + t) * HW + pix] = __float2half_rn(v);
}

// launch 2: merged prep. bx<512: per-p copyUa + weff. else: qe (warp per output).
__global__ void prep_kernel(const float* __restrict__ ua,
                            const float* __restrict__ ufw, const float* __restrict__ cqw,
                            const float* __restrict__ st_hat, const float* __restrict__ waw,
                            const float* __restrict__ wab, const float* __restrict__ uab,
                            const float* __restrict__ ufb, const float* __restrict__ cqb) {
    const int bx = blockIdx.x, tid = threadIdx.x;
    if (bx < NP) {
        const int p = bx;
        // copyUa
        for (int c = tid; c < CDIM; c += 128)
            g_Ah[p * KPAD + c] = __float2half_rn(ua[p * CDIM + c]);
        // weff: thread-per-tap, coalesced cqw reads
        for (int t = tid; t < TAPPAD; t += 128) {
            float s = 0.f;
            if (t < 121) {
                const float* ufp = ufw + p * 256;
                for (int q = 0; q < 256; q++)
                    s = fmaf(ufp[q], cqw[q * 121 + t], s);
            }
            g_Ah[p * KPAD + CDIM + t] = __float2half_rn(s);
        }
    } else {
        const int w = (bx - NP) * 4 + (tid >> 5);     // 0..8191
        const int lane = tid & 31;
        const int b = w >> 9, p = w & (NP - 1);
        float s = 0.f;
        for (int i = lane; i < 256; i += 32) {
            s = fmaf(st_hat[b * 256 + i], waw[p * 256 + i], s);
            s = fmaf(ufw[p * 256 + i], cqb[i], s);
        }
#pragma unroll
        for (int o = 16; o > 0; o >>= 1) s += __shfl_down_sync(0xFFFFFFFFu, s, o);
        if (lane == 0) g_qe[w] = s + wab[p] + uab[p] + ufb[p];
    }
}

// ================= fp16 mma score kernel (launch 3 — profiled) =================
// CTA = (b, 128-pix tile, p-quarter of 128). 8 warps: warp_m=wid&3 (32p), warp_n=wid>>2 (64pix).
__global__ __launch_bounds__(256, 2)
void score_kernel(const float* __restrict__ vaw) {
    extern __shared__ char smem[];
    __shared__ float qe_s[128], va_s[128];
    __shared__ float red[4][128];

    const int tid = threadIdx.x;
    const int wid = tid >> 5, lane = tid & 31;
    const int warp_m = wid & 3, warp_n = wid >> 2;
    const int g = lane >> 2, ti = lane & 3;
    const int b = blockIdx.y, tileY = blockIdx.x, pz = blockIdx.z;
    const int pixbase = tileY * 128;

    const uint32_t sbase = smem_u32(smem);

    if (tid < 128) {
        qe_s[tid] = g_qe[b * NP + pz * 128 + tid];
        va_s[tid] = vaw[pz * 128 + tid];
    }

    // cp.async indices: A 128 rows x 2x16B, B 16 rows x 16x16B
    const int arow = tid >> 1, agp = tid & 1;
    const __half* Asrc0 = g_Ah + (size_t)(pz * 128 + arow) * KPAD + agp * 8;
    const uint32_t Adst = arow * A_ROW_B + agp * 16;
    const int brow = tid >> 4, bgp = tid & 15;
    const __half* Bsrc0 = g_Bh + ((size_t)b * KPAD + brow) * HW + pixbase + bgp * 8;
    const uint32_t Bdst = A_STAGE_B + brow * B_ROW_B + bgp * 16;

    auto issue = [&](int ch) {
        const uint32_t st = sbase + (ch & 3) * STAGE_B;
        asm volatile("cp.async.cg.shared.global [%0], [%1], 16;"
                     :: "r"(st + Adst), "l"(Asrc0 + ch * 16) : "memory");
        asm volatile("cp.async.cg.shared.global [%0], [%1], 16;"
                     :: "r"(st + Bdst), "l"(Bsrc0 + (size_t)ch * 16 * HW) : "memory");
        asm volatile("cp.async.commit_group;" ::: "memory");
    };

    issue(0); issue(1); issue(2);

    const int mat = lane >> 3, mrow = lane & 7;
    const uint32_t aoff = (uint32_t)(warp_m * 32 + mrow + (mat & 1) * 8) * A_ROW_B + (mat >> 1) * 16;
    const uint32_t boff = A_STAGE_B + (uint32_t)(mrow + (mat & 1) * 8) * B_ROW_B
                        + (uint32_t)(warp_n * 64 + (mat >> 1) * 8) * 2;

    float acc[2][8][4];
#pragma unroll
    for (int t = 0; t < 2; t++)
#pragma unroll
        for (int u = 0; u < 8; u++)
#pragma unroll
            for (int c = 0; c < 4; c++) acc[t][u][c] = 0.f;

    for (int ch = 0; ch < NCHUNK; ch++) {
        asm volatile("cp.async.wait_group 2;" ::: "memory");
        __syncthreads();

        const uint32_t st = sbase + (ch & 3) * STAGE_B;
        uint32_t afr[2][4], bfr[4][4];
#pragma unroll
        for (int t = 0; t < 2; t++)
            asm volatile("ldmatrix.sync.aligned.m8n8.x4.shared.b16 {%0,%1,%2,%3}, [%4];"
                         : "=r"(afr[t][0]), "=r"(afr[t][1]), "=r"(afr[t][2]), "=r"(afr[t][3])
                         : "r"(st + aoff + t * 16 * A_ROW_B));
#pragma unroll
        for (int h = 0; h < 4; h++)
            asm volatile("ldmatrix.sync.aligned.m8n8.x4.trans.shared.b16 {%0,%1,%2,%3}, [%4];"
                         : "=r"(bfr[h][0]), "=r"(bfr[h][1]), "=r"(bfr[h][2]), "=r"(bfr[h][3])
                         : "r"(st + boff + h * 32));
#pragma unroll
        for (int t = 0; t < 2; t++)
#pragma unroll
            for (int u = 0; u < 8; u++) {
                const uint32_t b0 = bfr[u >> 1][(u & 1) * 2];
                const uint32_t b1 = bfr[u >> 1][(u & 1) * 2 + 1];
                asm volatile(
                    "mma.sync.aligned.m16n8k16.row.col.f32.f16.f16.f32 "
                    "{%0,%1,%2,%3}, {%4,%5,%6,%7}, {%8,%9}, {%0,%1,%2,%3};"
                    : "+f"(acc[t][u][0]), "+f"(acc[t][u][1]),
                      "+f"(acc[t][u][2]), "+f"(acc[t][u][3])
                    : "r"(afr[t][0]), "r"(afr[t][1]), "r"(afr[t][2]), "r"(afr[t][3]),
                      "r"(b0), "r"(b1));
            }

        if (ch + 3 < NCHUNK) issue(ch + 3);
        else asm volatile("cp.async.commit_group;" ::: "memory");
    }

    // epilogue
    float part[8][2];
#pragma unroll
    for (int u = 0; u < 8; u++) { part[u][0] = 0.f; part[u][1] = 0.f; }
#pragma unroll
    for (int t = 0; t < 2; t++) {
        const int p0 = warp_m * 32 + t * 16 + g;
        const float q0 = qe_s[p0],     v0 = va_s[p0];
        const float q1 = qe_s[p0 + 8], v1 = va_s[p0 + 8];
#pragma unroll
        for (int u = 0; u < 8; u++) {
            part[u][0] = fmaf(v0, tanhf(acc[t][u][0] + q0), part[u][0]);
            part[u][1] = fmaf(v0, tanhf(acc[t][u][1] + q0), part[u][1]);
            part[u][0] = fmaf(v1, tanhf(acc[t][u][2] + q1), part[u][0]);
            part[u][1] = fmaf(v1, tanhf(acc[t][u][3] + q1), part[u][1]);
        }
    }
#pragma unroll
    for (int u = 0; u < 8; u++)
#pragma unroll
        for (int j = 0; j < 2; j++) {
            part[u][j] += __shfl_down_sync(0xFFFFFFFFu, part[u][j], 16);
            part[u][j] += __shfl_down_sync(0xFFFFFFFFu, part[u][j], 8);
            part[u][j] += __shfl_down_sync(0xFFFFFFFFu, part[u][j], 4);
        }
    if (lane < 4) {
#pragma unroll
        for (int u = 0; u < 8; u++)
#pragma unroll
            for (int j = 0; j < 2; j++)
                red[warp_m][warp_n * 64 + u * 8 + ti * 2 + j] = part[u][j];
    }
    __syncthreads();
    if (tid < 128) {
        float s = red[0][tid] + red[1][tid] + red[2][tid] + red[3][tid];
        g_epart[pz][b * HW + pixbase + tid] = s;
    }
}

// ================= softmax / outputs =================
__global__ void softmax_kernel(const float* __restrict__ vab) {
    int b = blockIdx.x, tid = threadIdx.x;
    __shared__ float red[256];
    const float vb = vab[0];
    float local = 0.f;
    for (int i = tid; i < HW; i += 256) {
        int idx = b * HW + i;
        float v = expf(g_epart[0][idx] + g_epart[1][idx] +
                       g_epart[2][idx] + g_epart[3][idx] + vb);
        g_e[idx] = v;
        local += v;
    }
    red[tid] = local;
    __syncthreads();
    for (int s = 128; s > 0; s >>= 1) {
        if (tid < s) red[tid] += red[tid + s];
        __syncthreads();
    }
    if (tid == 0) g_S[b] = red[0] + 1e-8f;
}

__global__ void alpha_kernel(float* __restrict__ out_alpha) {
    int idx = blockIdx.x * blockDim.x + threadIdx.x;
    if (idx < BS * HW) out_alpha[idx] = g_e[idx] / g_S[idx >> 12];
}

__global__ void context_kernel(float* __restrict__ out) {
    int c = blockIdx.x, b = blockIdx.y;
    const __half2* xr = (const __half2*)(g_Bh + ((size_t)b * KPAD + c) * HW);
    const float* er = g_e + b * HW;
    float s = 0.f;
    for (int i = threadIdx.x; i < HW / 2; i += 128) {
        float2 xv = __half22float2(xr[i]);
        s = fmaf(xv.x, er[2 * i], s);
        s = fmaf(xv.y, er[2 * i + 1], s);
    }
    __shared__ float red[128];
    red[threadIdx.x] = s;
    __syncthreads();
    for (int st = 64; st > 0; st >>= 1) {
        if (threadIdx.x < st) red[threadIdx.x] += red[threadIdx.x + st];
        __syncthreads();
    }
    if (threadIdx.x == 0) out[b * CDIM + c] = red[0] / g_S[b];
}

// ================= launch =================
extern "C" void kernel_launch(void* const* d_in, const int* in_sizes, int n_in,
                              void* d_out, int out_size) {
    const float* x        = (const float*)d_in[0];
    const float* st_hat   = (const float*)d_in[1];
    const float* alpha    = (const float*)d_in[2];
    const float* convQ_w  = (const float*)d_in[3];
    const float* convQ_b  = (const float*)d_in[4];
    const float* Wa_w     = (const float*)d_in[5];
    const float* Wa_b     = (const float*)d_in[6];
    const float* convUa_w = (const float*)d_in[7];
    const float* convUa_b = (const float*)d_in[8];
    const float* Uf_w     = (const float*)d_in[9];
    const float* Uf_b     = (const float*)d_in[10];
    const float* Va_w     = (const float*)d_in[11];
    const float* Va_b     = (const float*)d_in[12];

    float* out_ctx   = (float*)d_out;
    float* out_alpha = (float*)d_out + BS * CDIM;

    const int dyn_bytes = NSTAGES * STAGE_B;   // 41984
    cudaFuncSetAttribute(score_kernel, cudaFuncAttributeMaxDynamicSharedMemorySize,
                         dyn_bytes);

    {   // launch 0
        dim3 g((CDIM * (HW / 4) + 255) / 256, BS);
        convx_kernel<<<g, 256>>>(x);
    }
    {   // launch 1
        dim3 g((TAPPAD * HW + 255) / 256, BS);
        taps_kernel<<<g, 256>>>(alpha);
    }
    // launch 2: merged prep (512 p-blocks + 2048 qe-blocks)
    prep_kernel<<<NP + 2048, 128>>>(convUa_w, Uf_w, convQ_w, st_hat, Wa_w, Wa_b,
                                    convUa_b, Uf_b, convQ_b);
    {   // launch 3 (profiled)
        dim3 gs(HW / 128, BS, 4);
        score_kernel<<<gs, 256, dyn_bytes>>>(Va_w);
    }
    softmax_kernel<<<BS, 256>>>(Va_b);                                            // 4
    alpha_kernel<<<(BS * HW + 255) / 256, 256>>>(out_alpha);                      // 5
    {   // launch 6
        dim3 gc(CDIM, BS);
        context_kernel<<<gc, 128>>>(out_ctx);
    }
}

// round 9
// speedup vs baseline: 4.9674x; 1.0549x over previous
#include <cuda_runtime.h>
#include <cuda_fp16.h>
#include <cstdint>
#include <math.h>

#define HW    4096
#define CDIM  684
#define NP    512
#define BS    16
#define KPAD  832            // 684 channels + 121 taps + 27 zero pad
#define NCHUNK 26            // K chunks of 32
#define TAPPAD 148

// smem stage layout (bytes), K-chunk = 32
#define A_ROW_B   80         // 32 halves (64B) + 16B pad
#define B_ROW_B   272        // 128 halves (256B) + 16B pad
#define A_STAGE_B (128 * A_ROW_B)            // 10240
#define B_STAGE_B (32 * B_ROW_B)             // 8704
#define STAGE_B   (A_STAGE_B + B_STAGE_B)    // 18944
#define NSTAGES   4

// -------- device scratch --------
__device__ __half g_Ah  [NP * KPAD];
__device__ __half g_Bh  [(size_t)BS * KPAD * HW];    // 109 MB
__device__ float  g_qe  [BS * NP];
__device__ float  g_epart[4][BS * HW];
__device__ float  g_e   [BS * HW];
__device__ float  g_ps  [BS * 32];
__device__ float  g_S   [BS];

__device__ __forceinline__ uint32_t smem_u32(const void* p) {
    uint32_t a;
    asm("{ .reg .u64 t; cvta.to.shared.u64 t, %1; cvt.u32.u64 %0, t; }" : "=r"(a) : "l"(p));
    return a;
}

// ================= prep kernels =================

__global__ void convx_kernel(const float* __restrict__ x) {
    int b = blockIdx.y;
    int i4 = blockIdx.x * blockDim.x + threadIdx.x;
    if (i4 >= CDIM * (HW / 4)) return;
    int c = i4 >> 10, pixq = i4 & 1023;
    float4 v = *(const float4*)(x + ((size_t)b * CDIM + c) * HW + pixq * 4);
    __half2* dst = (__half2*)(g_Bh + ((size_t)b * KPAD + c) * HW + pixq * 4);
    dst[0] = __floats2half2_rn(v.x, v.y);
    dst[1] = __floats2half2_rn(v.z, v.w);
}

__global__ void taps_kernel(const float* __restrict__ alpha) {
    int b = blockIdx.y;
    int j = blockIdx.x * blockDim.x + threadIdx.x;
    if (j >= TAPPAD * HW) return;
    int t = j >> 12, pix = j & (HW - 1);
    float v = 0.f;
    if (t < 121) {
        int dy = t / 11, dx = t - dy * 11;
        int y = (pix >> 7) + dy - 5, xx = (pix & 127) + dx - 5;
        if (y >= 0 && y < 32 && xx >= 0 && xx < 128) {
            const float* a = alpha + (size_t)b * 4 * HW + y * 128 + xx;
            v = a[0] + a[HW] + a[2 * HW] + a[3 * HW];
        }
    }
    g_Bh[((size_t)b * KPAD + CDIM + t) * HW + pix] = __float2half_rn(v);
}

__global__ void prep_kernel(const float* __restrict__ ua,
                            const float* __restrict__ ufw, const float* __restrict__ cqw,
                            const float* __restrict__ st_hat, const float* __restrict__ waw,
                            const float* __restrict__ wab, const float* __restrict__ uab,
                            const float* __restrict__ ufb, const float* __restrict__ cqb) {
    const int bx = blockIdx.x, tid = threadIdx.x;
    if (bx < NP) {
        const int p = bx;
        for (int c = tid; c < CDIM; c += 128)
            g_Ah[p * KPAD + c] = __float2half_rn(ua[p * CDIM + c]);
        for (int t = tid; t < TAPPAD; t += 128) {
            float s = 0.f;
            if (t < 121) {
                const float* ufp = ufw + p * 256;
                for (int q = 0; q < 256; q++)
                    s = fmaf(ufp[q], cqw[q * 121 + t], s);
            }
            g_Ah[p * KPAD + CDIM + t] = __float2half_rn(s);
        }
    } else {
        const int w = (bx - NP) * 4 + (tid >> 5);
        const int lane = tid & 31;
        const int b = w >> 9, p = w & (NP - 1);
        float s = 0.f;
        for (int i = lane; i < 256; i += 32) {
            s = fmaf(st_hat[b * 256 + i], waw[p * 256 + i], s);
            s = fmaf(ufw[p * 256 + i], cqb[i], s);
        }
#pragma unroll
        for (int o = 16; o > 0; o >>= 1) s += __shfl_down_sync(0xFFFFFFFFu, s, o);
        if (lane == 0) g_qe[w] = s + wab[p] + uab[p] + ufb[p];
    }
}

// ================= fp16 mma score kernel (launch 3) =================
// CTA = (b, 128-pix tile, p-quarter). 8 warps: warp_m=wid&3 (32p), warp_n=wid>>2 (64pix).
// K chunk = 32, 26 chunks, 4-stage cp.async ring.
__global__ __launch_bounds__(256, 2)
void score_kernel(const float* __restrict__ vaw) {
    extern __shared__ char smem[];
    __shared__ float qe_s[128], va_s[128];
    __shared__ float red[4][128];

    const int tid = threadIdx.x;
    const int wid = tid >> 5, lane = tid & 31;
    const int warp_m = wid & 3, warp_n = wid >> 2;
    const int g = lane >> 2, ti = lane & 3;
    const int b = blockIdx.y, tileY = blockIdx.x, pz = blockIdx.z;
    const int pixbase = tileY * 128;

    const uint32_t sbase = smem_u32(smem);

    if (tid < 128) {
        qe_s[tid] = g_qe[b * NP + pz * 128 + tid];
        va_s[tid] = vaw[pz * 128 + tid];
    }

    // cp.async: A 128 rows x 4x16B (512 groups), B 32 rows x 16x16B (512 groups); 2 each/thread
    const int ar0 = tid >> 2,          ag0 = tid & 3;
    const int ar1 = (tid + 256) >> 2,  ag1 = (tid + 256) & 3;
    const __half* Asrc0 = g_Ah + (size_t)(pz * 128 + ar0) * KPAD + ag0 * 8;
    const __half* Asrc1 = g_Ah + (size_t)(pz * 128 + ar1) * KPAD + ag1 * 8;
    const uint32_t Adst0 = ar0 * A_ROW_B + ag0 * 16;
    const uint32_t Adst1 = ar1 * A_ROW_B + ag1 * 16;
    const int br0 = tid >> 4,          bg0 = tid & 15;
    const int br1 = (tid + 256) >> 4,  bg1 = (tid + 256) & 15;
    const __half* Bsrc0 = g_Bh + ((size_t)b * KPAD + br0) * HW + pixbase + bg0 * 8;
    const __half* Bsrc1 = g_Bh + ((size_t)b * KPAD + br1) * HW + pixbase + bg1 * 8;
    const uint32_t Bdst0 = A_STAGE_B + br0 * B_ROW_B + bg0 * 16;
    const uint32_t Bdst1 = A_STAGE_B + br1 * B_ROW_B + bg1 * 16;

    auto issue = [&](int ch) {
        const uint32_t st = sbase + (ch & 3) * STAGE_B;
        const size_t ko = (size_t)ch * 32;
        asm volatile("cp.async.cg.shared.global [%0], [%1], 16;"
                     :: "r"(st + Adst0), "l"(Asrc0 + ko) : "memory");
        asm volatile("cp.async.cg.shared.global [%0], [%1], 16;"
                     :: "r"(st + Adst1), "l"(Asrc1 + ko) : "memory");
        asm volatile("cp.async.cg.shared.global [%0], [%1], 16;"
                     :: "r"(st + Bdst0), "l"(Bsrc0 + ko * HW) : "memory");
        asm volatile("cp.async.cg.shared.global [%0], [%1], 16;"
                     :: "r"(st + Bdst1), "l"(Bsrc1 + ko * HW) : "memory");
        asm volatile("cp.async.commit_group;" ::: "memory");
    };

    issue(0); issue(1); issue(2);

    const int mat = lane >> 3, mrow = lane & 7;
    const uint32_t aoff = (uint32_t)(warp_m * 32 + mrow + (mat & 1) * 8) * A_ROW_B + (mat >> 1) * 16;
    const uint32_t boff = A_STAGE_B + (uint32_t)(mrow + (mat & 1) * 8) * B_ROW_B
                        + (uint32_t)(warp_n * 64 + (mat >> 1) * 8) * 2;

    float acc[2][8][4];
#pragma unroll
    for (int t = 0; t < 2; t++)
#pragma unroll
        for (int u = 0; u < 8; u++)
#pragma unroll
            for (int c = 0; c < 4; c++) acc[t][u][c] = 0.f;

    for (int ch = 0; ch < NCHUNK; ch++) {
        asm volatile("cp.async.wait_group 2;" ::: "memory");
        __syncthreads();

        const uint32_t st = sbase + (ch & 3) * STAGE_B;
        if (ch + 3 < NCHUNK) issue(ch + 3);
        else asm volatile("cp.async.commit_group;" ::: "memory");

#pragma unroll
        for (int kh = 0; kh < 2; kh++) {
            uint32_t afr[2][4], bfr[4][4];
#pragma unroll
            for (int t = 0; t < 2; t++)
                asm volatile("ldmatrix.sync.aligned.m8n8.x4.shared.b16 {%0,%1,%2,%3}, [%4];"
                             : "=r"(afr[t][0]), "=r"(afr[t][1]), "=r"(afr[t][2]), "=r"(afr[t][3])
                             : "r"(st + aoff + t * 16 * A_ROW_B + kh * 32));
#pragma unroll
            for (int h = 0; h < 4; h++)
                asm volatile("ldmatrix.sync.aligned.m8n8.x4.trans.shared.b16 {%0,%1,%2,%3}, [%4];"
                             : "=r"(bfr[h][0]), "=r"(bfr[h][1]), "=r"(bfr[h][2]), "=r"(bfr[h][3])
                             : "r"(st + boff + kh * 16 * B_ROW_B + h * 32));
#pragma unroll
            for (int t = 0; t < 2; t++)
#pragma unroll
                for (int u = 0; u < 8; u++) {
                    const uint32_t b0 = bfr[u >> 1][(u & 1) * 2];
                    const uint32_t b1 = bfr[u >> 1][(u & 1) * 2 + 1];
                    asm volatile(
                        "mma.sync.aligned.m16n8k16.row.col.f32.f16.f16.f32 "
                        "{%0,%1,%2,%3}, {%4,%5,%6,%7}, {%8,%9}, {%0,%1,%2,%3};"
                        : "+f"(acc[t][u][0]), "+f"(acc[t][u][1]),
                          "+f"(acc[t][u][2]), "+f"(acc[t][u][3])
                        : "r"(afr[t][0]), "r"(afr[t][1]), "r"(afr[t][2]), "r"(afr[t][3]),
                          "r"(b0), "r"(b1));
                }
        }
    }

    // epilogue
    float part[8][2];
#pragma unroll
    for (int u = 0; u < 8; u++) { part[u][0] = 0.f; part[u][1] = 0.f; }
#pragma unroll
    for (int t = 0; t < 2; t++) {
        const int p0 = warp_m * 32 + t * 16 + g;
        const float q0 = qe_s[p0],     v0 = va_s[p0];
        const float q1 = qe_s[p0 + 8], v1 = va_s[p0 + 8];
#pragma unroll
        for (int u = 0; u < 8; u++) {
            part[u][0] = fmaf(v0, tanhf(acc[t][u][0] + q0), part[u][0]);
            part[u][1] = fmaf(v0, tanhf(acc[t][u][1] + q0), part[u][1]);
            part[u][0] = fmaf(v1, tanhf(acc[t][u][2] + q1), part[u][0]);
            part[u][1] = fmaf(v1, tanhf(acc[t][u][3] + q1), part[u][1]);
        }
    }
#pragma unroll
    for (int u = 0; u < 8; u++)
#pragma unroll
        for (int j = 0; j < 2; j++) {
            part[u][j] += __shfl_down_sync(0xFFFFFFFFu, part[u][j], 16);
            part[u][j] += __shfl_down_sync(0xFFFFFFFFu, part[u][j], 8);
            part[u][j] += __shfl_down_sync(0xFFFFFFFFu, part[u][j], 4);
        }
    if (lane < 4) {
#pragma unroll
        for (int u = 0; u < 8; u++)
#pragma unroll
            for (int j = 0; j < 2; j++)
                red[warp_m][warp_n * 64 + u * 8 + ti * 2 + j] = part[u][j];
    }
    __syncthreads();
    if (tid < 128) {
        float s = red[0][tid] + red[1][tid] + red[2][tid] + red[3][tid];
        g_epart[pz][b * HW + pixbase + tid] = s;
    }
}

// ================= softmax / outputs =================
// pass1: exp + per-tile partial sums. grid (32, BS), 128 thr.
__global__ void softmax1_kernel(const float* __restrict__ vab) {
    const int b = blockIdx.y, tile = blockIdx.x, tid = threadIdx.x;
    const int idx = b * HW + tile * 128 + tid;
    float v = expf(g_epart[0][idx] + g_epart[1][idx] +
                   g_epart[2][idx] + g_epart[3][idx] + vab[0]);
    g_e[idx] = v;
#pragma unroll
    for (int o = 16; o > 0; o >>= 1) v += __shfl_down_sync(0xFFFFFFFFu, v, o);
    __shared__ float red[4];
    if ((tid & 31) == 0) red[tid >> 5] = v;
    __syncthreads();
    if (tid == 0) g_ps[b * 32 + tile] = red[0] + red[1] + red[2] + red[3];
}

// pass2: grid BS, 32 thr
__global__ void softmax2_kernel() {
    const int b = blockIdx.x, lane = threadIdx.x;
    float v = g_ps[b * 32 + lane];
#pragma unroll
    for (int o = 16; o > 0; o >>= 1) v += __shfl_down_sync(0xFFFFFFFFu, v, o);
    if (lane == 0) g_S[b] = v + 1e-8f;
}

__global__ void alpha_kernel(float* __restrict__ out_alpha) {
    int idx = blockIdx.x * blockDim.x + threadIdx.x;
    if (idx < BS * HW) out_alpha[idx] = g_e[idx] / g_S[idx >> 12];
}

__global__ void context_kernel(float* __restrict__ out) {
    int c = blockIdx.x, b = blockIdx.y;
    const __half2* xr = (const __half2*)(g_Bh + ((size_t)b * KPAD + c) * HW);
    const float* er = g_e + b * HW;
    float s = 0.f;
    for (int i = threadIdx.x; i < HW / 2; i += 128) {
        float2 xv = __half22float2(xr[i]);
        s = fmaf(xv.x, er[2 * i], s);
        s = fmaf(xv.y, er[2 * i + 1], s);
    }
    __shared__ float red[128];
    red[threadIdx.x] = s;
    __syncthreads();
    for (int st = 64; st > 0; st >>= 1) {
        if (threadIdx.x < st) red[threadIdx.x] += red[threadIdx.x + st];
        __syncthreads();
    }
    if (threadIdx.x == 0) out[b * CDIM + c] = red[0] / g_S[b];
}

// ================= launch =================
extern "C" void kernel_launch(void* const* d_in, const int* in_sizes, int n_in,
                              void* d_out, int out_size) {
    const float* x        = (const float*)d_in[0];
    const float* st_hat   = (const float*)d_in[1];
    const float* alpha    = (const float*)d_in[2];
    const float* convQ_w  = (const float*)d_in[3];
    const float* convQ_b  = (const float*)d_in[4];
    const float* Wa_w     = (const float*)d_in[5];
    const float* Wa_b     = (const float*)d_in[6];
    const float* convUa_w = (const float*)d_in[7];
    const float* convUa_b = (const float*)d_in[8];
    const float* Uf_w     = (const float*)d_in[9];
    const float* Uf_b     = (const float*)d_in[10];
    const float* Va_w     = (const float*)d_in[11];
    const float* Va_b     = (const float*)d_in[12];

    float* out_ctx   = (float*)d_out;
    float* out_alpha = (float*)d_out + BS * CDIM;

    const int dyn_bytes = NSTAGES * STAGE_B;   // 75776
    cudaFuncSetAttribute(score_kernel, cudaFuncAttributeMaxDynamicSharedMemorySize,
                         dyn_bytes);

    {   // launch 0
        dim3 g((CDIM * (HW / 4) + 255) / 256, BS);
        convx_kernel<<<g, 256>>>(x);
    }
    {   // launch 1
        dim3 g((TAPPAD * HW + 255) / 256, BS);
        taps_kernel<<<g, 256>>>(alpha);
    }
    // launch 2
    prep_kernel<<<NP + 2048, 128>>>(convUa_w, Uf_w, convQ_w, st_hat, Wa_w, Wa_b,
                                    convUa_b, Uf_b, convQ_b);
    {   // launch 3 (profiled)
        dim3 gs(HW / 128, BS, 4);
        score_kernel<<<gs, 256, dyn_bytes>>>(Va_w);
    }
    {   // launch 4
        dim3 g(32, BS);
        softmax1_kernel<<<g, 128>>>(Va_b);
    }
    softmax2_kernel<<<BS, 32>>>();                                                // 5
    alpha_kernel<<<(BS * HW + 255) / 256, 256>>>(out_alpha);                      // 6
    {   // launch 7
        dim3 gc(CDIM, BS);
        context_kernel<<<gc, 128>>>(out_ctx);
    }
}